// round 3
// baseline (speedup 1.0000x reference)
#include <cuda_runtime.h>
#include <math.h>

#define NN 50000
#define EE 800000
#define BB 64
#define OBSD 128
#define MHD 256
#define NAD 16

// ---------------- scratch (static device arrays; no allocation) ----------------
__device__ float    g_x[NN * 128];      // layer input / aggregated output (in-place)
__device__ float    g_h[NN * 128];      // h = x @ W for current layer
__device__ float    g_as[NN * 2];
__device__ float    g_ad[NN * 2];
__device__ float    g_eself[NN * 2];
__device__ float    g_mfl[NN * 2];
__device__ float    g_denom[NN * 2];
__device__ unsigned g_menc[NN * 2];
__device__ float    g_ex[EE * 2];
__device__ float    g_pool[BB * 64];
__device__ float    g_cnt[BB];

// ---------------- helpers ----------------
__device__ __forceinline__ unsigned encf(float f) {
    unsigned u = __float_as_uint(f);
    return (u & 0x80000000u) ? ~u : (u | 0x80000000u);
}
__device__ __forceinline__ float decf(unsigned u) {
    return (u & 0x80000000u) ? __uint_as_float(u & 0x7fffffffu) : __uint_as_float(~u);
}
__device__ __forceinline__ float lrelu(float v) { return v > 0.f ? v : 0.2f * v; }

__device__ __forceinline__ void red4(float* p, float a, float b, float c, float d) {
    asm volatile("red.global.add.v4.f32 [%0], {%1,%2,%3,%4};"
                 :: "l"(p), "f"(a), "f"(b), "f"(c), "f"(d) : "memory");
}

// ---------------- k1: h = x @ W, plus alpha_src/alpha_dst per node, self-edge init ----
template <int FIN, int HC, int H>
__global__ void k_lin(const float* __restrict__ xin, const float* __restrict__ W,
                      const float* __restrict__ asrc, const float* __restrict__ adst) {
    constexpr int C   = HC / H;
    constexpr int KC  = (FIN < 64) ? FIN : 64;
    constexpr int NPB = 8;
    __shared__ float Wsh[KC * HC];
    __shared__ float xsh[NPB * KC];
    __shared__ float red_s[HC / 32];
    __shared__ float red_d[HC / 32];

    const float* x = xin ? xin : g_x;
    int tid  = threadIdx.x;           // 0..HC-1
    int head = tid / C, cc = tid % C;
    float av = asrc[head * C + cc];
    float bv = adst[head * C + cc];

    int ngroups = (NN + NPB - 1) / NPB;
    for (int g = blockIdx.x; g < ngroups; g += gridDim.x) {
        int base = g * NPB;
        float acc[NPB];
#pragma unroll
        for (int i = 0; i < NPB; i++) acc[i] = 0.f;

        for (int k0 = 0; k0 < FIN; k0 += KC) {
            for (int kk = 0; kk < KC; kk++) Wsh[kk * HC + tid] = W[(k0 + kk) * HC + tid];
            for (int idx = tid; idx < NPB * KC; idx += HC) {
                int ni = base + idx / KC;
                xsh[idx] = (ni < NN) ? x[ni * FIN + k0 + (idx % KC)] : 0.f;
            }
            __syncthreads();
            for (int kk = 0; kk < KC; kk++) {
                float w = Wsh[kk * HC + tid];
#pragma unroll
                for (int i = 0; i < NPB; i++) acc[i] += xsh[i * KC + kk] * w;
            }
            __syncthreads();
        }

        for (int i = 0; i < NPB; i++) {
            int n = base + i;
            if (n >= NN) break;
            g_h[n * HC + tid] = acc[i];
            float vs = acc[i] * av, vd = acc[i] * bv;
#pragma unroll
            for (int o = 16; o > 0; o >>= 1) {
                vs += __shfl_down_sync(0xffffffffu, vs, o);
                vd += __shfl_down_sync(0xffffffffu, vd, o);
            }
            if ((tid & 31) == 0) { red_s[tid >> 5] = vs; red_d[tid >> 5] = vd; }
            __syncthreads();
            if (tid < H) {
                constexpr int WPH = C / 32;
                float s = 0.f, d = 0.f;
#pragma unroll
                for (int w = 0; w < WPH; w++) { s += red_s[tid * WPH + w]; d += red_d[tid * WPH + w]; }
                g_as[n * H + tid] = s;
                g_ad[n * H + tid] = d;
                float es = lrelu(s + d);              // self-loop edge value
                g_eself[n * H + tid] = es;
                g_menc[n * H + tid]  = encf(es);      // init max with self edge
            }
            __syncthreads();
        }
    }
}

// ---------------- k2: segment max over dst (atomicMax on ordered uint) ----------------
template <int H>
__global__ void k_edge_max(const int* __restrict__ ei) {
    int total = EE * H;
    for (int idx = blockIdx.x * blockDim.x + threadIdx.x; idx < total; idx += gridDim.x * blockDim.x) {
        int e = idx / H, hh = idx - e * H;
        int s = ei[e], d = ei[EE + e];
        float v = lrelu(g_as[s * H + hh] + g_ad[d * H + hh]);
        atomicMax(&g_menc[d * H + hh], encf(v));
    }
}

// ---------------- k3: decode max; init denom + out with self contribution ----------------
template <int HC, int H>
__global__ void k_self() {
    constexpr int C = HC / H;
    int total = NN * HC;
    for (int idx = blockIdx.x * blockDim.x + threadIdx.x; idx < total; idx += gridDim.x * blockDim.x) {
        int n = idx / HC, c = idx - n * HC;
        int head = c / C;
        float m  = decf(g_menc[n * H + head]);
        float ws = expf(g_eself[n * H + head] - m);   // self-edge weight (unnormalized)
        g_x[idx] = ws * g_h[idx];
        if ((c % C) == 0) { g_mfl[n * H + head] = m; g_denom[n * H + head] = ws; }
    }
}

// ---------------- k4: ex = exp(e - max[dst]); accumulate denom ----------------
template <int H>
__global__ void k_edge_exp(const int* __restrict__ ei) {
    int total = EE * H;
    for (int idx = blockIdx.x * blockDim.x + threadIdx.x; idx < total; idx += gridDim.x * blockDim.x) {
        int e = idx / H, hh = idx - e * H;
        int s = ei[e], d = ei[EE + e];
        float v  = lrelu(g_as[s * H + hh] + g_ad[d * H + hh]);
        float ex = expf(v - g_mfl[d * H + hh]);
        g_ex[e * H + hh] = ex;
        atomicAdd(&g_denom[d * H + hh], ex);
    }
}

// ---------------- k6: out[dst] += ex * h[src] (vectorized global reductions) ----------------
template <int HC, int H>
__global__ void k_edge_msg(const int* __restrict__ ei) {
    constexpr int C = HC / H;
    constexpr int Q = HC / 4;
    long long total = (long long)EE * Q;
    for (long long idx = (long long)blockIdx.x * blockDim.x + threadIdx.x; idx < total;
         idx += (long long)gridDim.x * blockDim.x) {
        int e  = (int)(idx / Q);
        int q  = (int)(idx - (long long)e * Q);
        int c4 = q * 4;
        int head = c4 / C;
        int s = ei[e], d = ei[EE + e];
        float w = g_ex[e * H + head];
        float4 hv = *reinterpret_cast<const float4*>(g_h + (size_t)s * HC + c4);
        red4(g_x + (size_t)d * HC + c4, w * hv.x, w * hv.y, w * hv.z, w * hv.w);
    }
}

// ---------------- k7: normalize, add bias, optional ELU ----------------
template <int HC, int H, bool ACT>
__global__ void k_final(const float* __restrict__ bias) {
    constexpr int C = HC / H;
    int total = NN * HC;
    for (int idx = blockIdx.x * blockDim.x + threadIdx.x; idx < total; idx += gridDim.x * blockDim.x) {
        int n = idx / HC, c = idx - n * HC;
        int head = c / C;
        float v = g_x[idx] / (g_denom[n * H + head] + 1e-16f) + bias[c];
        if (ACT) v = v > 0.f ? v : expm1f(v);
        g_x[idx] = v;
    }
}

// ---------------- pooling ----------------
__global__ void k_pool_zero() {
    int idx = blockIdx.x * blockDim.x + threadIdx.x;
    if (idx < BB * 64) g_pool[idx] = 0.f;
    if (idx < BB) g_cnt[idx] = 0.f;
}

__global__ void k_pool(const int* __restrict__ batch) {
    int total = NN * 16;
    for (int idx = blockIdx.x * blockDim.x + threadIdx.x; idx < total; idx += gridDim.x * blockDim.x) {
        int n = idx / 16, q = idx - n * 16;
        int b = batch[n];
        float4 v = *reinterpret_cast<const float4*>(g_x + (size_t)n * 64 + q * 4);
        red4(g_pool + b * 64 + q * 4, v.x, v.y, v.z, v.w);
        if (q == 0) atomicAdd(&g_cnt[b], 1.0f);
    }
}

// ---------------- MLP head (one block per batch row) ----------------
__global__ void k_mlp(const float* __restrict__ obs,
                      const float* __restrict__ Ws1, const float* __restrict__ bs1,
                      const float* __restrict__ lng, const float* __restrict__ lnb,
                      const float* __restrict__ Ws2, const float* __restrict__ bs2,
                      const float* __restrict__ Wa,  const float* __restrict__ ba,
                      const float* __restrict__ Wc,  const float* __restrict__ bc,
                      float* __restrict__ out) {
    __shared__ float comb[64 + OBSD];
    __shared__ float hb[MHD];
    __shared__ float h2[MHD];
    __shared__ float rb[8];
    __shared__ float stats[2];

    int b = blockIdx.x;
    int tid = threadIdx.x;

    if (tid < 64)            comb[tid] = g_pool[b * 64 + tid] / fmaxf(g_cnt[b], 1.0f);
    else if (tid < 64 + OBSD) comb[tid] = obs[b * OBSD + (tid - 64)];
    __syncthreads();

    float s = bs1[tid];
    for (int k = 0; k < 64 + OBSD; k++) s += comb[k] * Ws1[k * MHD + tid];

    // mean
    float v = s;
#pragma unroll
    for (int o = 16; o > 0; o >>= 1) v += __shfl_down_sync(0xffffffffu, v, o);
    if ((tid & 31) == 0) rb[tid >> 5] = v;
    __syncthreads();
    if (tid == 0) { float t = 0.f; for (int w = 0; w < 8; w++) t += rb[w]; stats[0] = t / MHD; }
    __syncthreads();
    float mu = stats[0];
    // var
    float dv = s - mu;
    v = dv * dv;
#pragma unroll
    for (int o = 16; o > 0; o >>= 1) v += __shfl_down_sync(0xffffffffu, v, o);
    if ((tid & 31) == 0) rb[tid >> 5] = v;
    __syncthreads();
    if (tid == 0) { float t = 0.f; for (int w = 0; w < 8; w++) t += rb[w]; stats[1] = t / MHD; }
    __syncthreads();

    float hn = dv * rsqrtf(stats[1] + 1e-5f) * lng[tid] + lnb[tid];
    hb[tid] = fmaxf(hn, 0.f);
    __syncthreads();

    float s2 = bs2[tid];
    for (int k = 0; k < MHD; k++) s2 += hb[k] * Ws2[k * MHD + tid];
    h2[tid] = fmaxf(s2, 0.f);
    __syncthreads();

    if (tid < NAD) {
        float t = ba[tid];
        for (int k = 0; k < MHD; k++) t += h2[k] * Wa[k * NAD + tid];
        out[b * NAD + tid] = t;
    }
    if (tid == NAD) {
        float t = bc[0];
        for (int k = 0; k < MHD; k++) t += h2[k] * Wc[k];
        out[BB * NAD + b] = t;
    }
}

// ---------------- launch ----------------
static inline int gs(long long n) { return (int)((n + 255) / 256); }

extern "C" void kernel_launch(void* const* d_in, const int* in_sizes, int n_in,
                              void* d_out, int out_size) {
    const float* obs   = (const float*)d_in[0];
    const float* nf    = (const float*)d_in[1];
    const int*   ei    = (const int*)  d_in[2];
    const int*   batch = (const int*)  d_in[3];
    const float* W0 = (const float*)d_in[4];
    const float* as0 = (const float*)d_in[5];
    const float* ad0 = (const float*)d_in[6];
    const float* b0  = (const float*)d_in[7];
    const float* W1 = (const float*)d_in[8];
    const float* as1 = (const float*)d_in[9];
    const float* ad1 = (const float*)d_in[10];
    const float* b1  = (const float*)d_in[11];
    const float* W2 = (const float*)d_in[12];
    const float* as2 = (const float*)d_in[13];
    const float* ad2 = (const float*)d_in[14];
    const float* b2  = (const float*)d_in[15];
    const float* Ws1 = (const float*)d_in[16];
    const float* bs1 = (const float*)d_in[17];
    const float* lng = (const float*)d_in[18];
    const float* lnb = (const float*)d_in[19];
    const float* Ws2 = (const float*)d_in[20];
    const float* bs2 = (const float*)d_in[21];
    const float* Wa  = (const float*)d_in[22];
    const float* ba  = (const float*)d_in[23];
    const float* Wc  = (const float*)d_in[24];
    const float* bc  = (const float*)d_in[25];
    float* out = (float*)d_out;

    const int NG = (NN + 7) / 8;   // 6250 node groups

    // ---- GAT layer 0: in=8 -> H=2,C=64 concat, ELU ----
    k_lin<8, 128, 2><<<NG, 128>>>(nf, W0, as0, ad0);
    k_edge_max<2><<<gs((long long)EE * 2), 256>>>(ei);
    k_self<128, 2><<<gs((long long)NN * 128), 256>>>();
    k_edge_exp<2><<<gs((long long)EE * 2), 256>>>(ei);
    k_edge_msg<128, 2><<<gs((long long)EE * 32), 256>>>(ei);
    k_final<128, 2, true><<<gs((long long)NN * 128), 256>>>(b0);

    // ---- GAT layer 1: in=128 -> H=2,C=64 concat, ELU ----
    k_lin<128, 128, 2><<<NG, 128>>>(nullptr, W1, as1, ad1);
    k_edge_max<2><<<gs((long long)EE * 2), 256>>>(ei);
    k_self<128, 2><<<gs((long long)NN * 128), 256>>>();
    k_edge_exp<2><<<gs((long long)EE * 2), 256>>>(ei);
    k_edge_msg<128, 2><<<gs((long long)EE * 32), 256>>>(ei);
    k_final<128, 2, true><<<gs((long long)NN * 128), 256>>>(b1);

    // ---- GAT layer 2: in=128 -> H=1,C=64, no concat, no act ----
    k_lin<128, 64, 1><<<NG, 64>>>(nullptr, W2, as2, ad2);
    k_edge_max<1><<<gs((long long)EE), 256>>>(ei);
    k_self<64, 1><<<gs((long long)NN * 64), 256>>>();
    k_edge_exp<1><<<gs((long long)EE), 256>>>(ei);
    k_edge_msg<64, 1><<<gs((long long)EE * 16), 256>>>(ei);
    k_final<64, 1, false><<<gs((long long)NN * 64), 256>>>(b2);

    // ---- global mean pool ----
    k_pool_zero<<<gs(BB * 64), 256>>>();
    k_pool<<<gs((long long)NN * 16), 256>>>(batch);

    // ---- MLP head ----
    k_mlp<<<BB, MHD>>>(obs, Ws1, bs1, lng, lnb, Ws2, bs2, Wa, ba, Wc, bc, out);
}

// round 4
// speedup vs baseline: 1.7035x; 1.7035x over previous
#include <cuda_runtime.h>
#include <math.h>

#define NN 50000
#define EE 800000
#define BB 64
#define OBSD 128
#define MHD 256
#define NAD 16

// ---------------- scratch ----------------
__device__ float g_x[NN * 128];
__device__ float g_h[NN * 128];
__device__ float g_as[NN * 2];
__device__ float g_ad[NN * 2];
__device__ float g_es[NN * 2];
__device__ int   g_deg[NN + 1];
__device__ int   g_off[NN + 1];
__device__ int   g_cur[NN];
__device__ int   g_csr[EE];
__device__ int   g_bsum[128];
__device__ float g_pool[BB * 64];
__device__ float g_cnt[BB];

__device__ __forceinline__ float lrelu(float v) { return v > 0.f ? v : 0.2f * v; }

__device__ __forceinline__ void red4(float* p, float a, float b, float c, float d) {
    asm volatile("red.global.add.v4.f32 [%0], {%1,%2,%3,%4};"
                 :: "l"(p), "f"(a), "f"(b), "f"(c), "f"(d) : "memory");
}

// =================== CSR build ===================
__global__ void k_zero_deg() {
    for (int i = blockIdx.x * blockDim.x + threadIdx.x; i <= NN; i += gridDim.x * blockDim.x)
        g_deg[i] = 0;
}
__global__ void k_hist(const int* __restrict__ ei) {
    for (int e = blockIdx.x * blockDim.x + threadIdx.x; e < EE; e += gridDim.x * blockDim.x)
        atomicAdd(&g_deg[ei[EE + e]], 1);
}
// blocks of 512, 98 blocks cover 50176
__global__ void k_scan1() {
    __shared__ int sh[512];
    int tid = threadIdx.x;
    int i = blockIdx.x * 512 + tid;
    int v = (i < NN) ? g_deg[i] : 0;
    sh[tid] = v;
    __syncthreads();
    for (int o = 1; o < 512; o <<= 1) {
        int t = (tid >= o) ? sh[tid - o] : 0;
        __syncthreads();
        sh[tid] += t;
        __syncthreads();
    }
    if (i < NN) g_off[i] = sh[tid] - v;       // exclusive
    if (tid == 511) g_bsum[blockIdx.x] = sh[511];
}
__global__ void k_scan2() {
    __shared__ int sh[128];
    int tid = threadIdx.x;
    int v = (tid < 98) ? g_bsum[tid] : 0;
    sh[tid] = v;
    __syncthreads();
    for (int o = 1; o < 128; o <<= 1) {
        int t = (tid >= o) ? sh[tid - o] : 0;
        __syncthreads();
        sh[tid] += t;
        __syncthreads();
    }
    if (tid < 98) g_bsum[tid] = sh[tid] - v;  // exclusive
}
__global__ void k_scan3() {
    int tid = threadIdx.x;
    int i = blockIdx.x * 512 + tid;
    if (i < NN) {
        int o = g_off[i] + g_bsum[blockIdx.x];
        g_off[i] = o;
        g_cur[i] = o;
    }
    if (i == 0) g_off[NN] = EE;
}
__global__ void k_fill(const int* __restrict__ ei) {
    for (int e = blockIdx.x * blockDim.x + threadIdx.x; e < EE; e += gridDim.x * blockDim.x) {
        int d = ei[EE + e];
        int pos = atomicAdd(&g_cur[d], 1);
        g_csr[pos] = ei[e];
    }
}

// =================== epilogue helper: alpha dots ===================
template <int H, int VEC>
__device__ __forceinline__ void alpha_epilogue(int node, int lane, int head,
                                               const float* acc, const float* asv, const float* adv) {
    float vs = 0.f, vd = 0.f;
#pragma unroll
    for (int v = 0; v < VEC; v++) { vs += acc[v] * asv[v]; vd += acc[v] * adv[v]; }
    constexpr int RO = (H == 2) ? 8 : 16;
#pragma unroll
    for (int o = RO; o > 0; o >>= 1) {
        vs += __shfl_down_sync(0xffffffffu, vs, o);
        vd += __shfl_down_sync(0xffffffffu, vd, o);
    }
    if ((lane & ((H == 2) ? 15 : 31)) == 0) {
        g_as[node * H + head] = vs;
        g_ad[node * H + head] = vd;
        g_es[node * H + head] = lrelu(vs + vd);
    }
}

// =================== layer-0 GEMM (FIN=8 -> HC=128, H=2) ===================
__global__ void k_gemm0(const float* __restrict__ xin, const float* __restrict__ W,
                        const float* __restrict__ asrc, const float* __restrict__ adst) {
    __shared__ float Wsh[8 * 128];
    int tid = threadIdx.x, lane = tid & 31, wp = tid >> 5;
    for (int i = tid; i < 8 * 128; i += 256) Wsh[i] = W[i];
    float asv[4], adv[4];
#pragma unroll
    for (int v = 0; v < 4; v++) { asv[v] = asrc[lane * 4 + v]; adv[v] = adst[lane * 4 + v]; }
    int head = lane >> 4;
    __syncthreads();

    for (int node = blockIdx.x * 8 + wp; node < NN; node += gridDim.x * 8) {
        float xk[8];
#pragma unroll
        for (int k = 0; k < 8; k++) xk[k] = __ldg(&xin[node * 8 + k]);
        float acc[4] = {0.f, 0.f, 0.f, 0.f};
#pragma unroll
        for (int k = 0; k < 8; k++) {
            float4 w = *reinterpret_cast<const float4*>(&Wsh[k * 128 + lane * 4]);
            acc[0] += xk[k] * w.x; acc[1] += xk[k] * w.y;
            acc[2] += xk[k] * w.z; acc[3] += xk[k] * w.w;
        }
        *reinterpret_cast<float4*>(&g_h[(size_t)node * 128 + lane * 4]) =
            make_float4(acc[0], acc[1], acc[2], acc[3]);
        alpha_epilogue<2, 4>(node, lane, head, acc, asv, adv);
    }
}

// =================== big GEMM (FIN=128 -> HC, H) ===================
template <int HC, int H>
__global__ void k_gemm128(const float* __restrict__ W,
                          const float* __restrict__ asrc, const float* __restrict__ adst) {
    constexpr int VEC = HC / 32;
    constexpr int KT = 32;
    constexpr int NCH = 64;
    __shared__ float Wsh[KT * HC];
    __shared__ float xsh[NCH * KT];
    int tid = threadIdx.x, lane = tid & 31, wp = tid >> 5;   // 8 warps
    int head = (H == 2) ? (lane >> 4) : 0;
    float asv[VEC], adv[VEC];
#pragma unroll
    for (int v = 0; v < VEC; v++) { asv[v] = asrc[lane * VEC + v]; adv[v] = adst[lane * VEC + v]; }

    for (int base = blockIdx.x * NCH; base < NN; base += gridDim.x * NCH) {
        float acc[8][VEC];
#pragma unroll
        for (int n = 0; n < 8; n++)
#pragma unroll
            for (int v = 0; v < VEC; v++) acc[n][v] = 0.f;

        for (int k0 = 0; k0 < 128; k0 += KT) {
            for (int i = tid; i < KT * HC; i += 256)
                Wsh[i] = W[((i / HC) + k0) * HC + (i % HC)];
            for (int i = tid; i < NCH * KT; i += 256) {
                int n = base + i / KT;
                xsh[i] = (n < NN) ? g_x[(size_t)n * 128 + k0 + (i % KT)] : 0.f;
            }
            __syncthreads();
#pragma unroll
            for (int kk = 0; kk < KT; kk += 4) {
                float wv[4][VEC];
#pragma unroll
                for (int j = 0; j < 4; j++)
#pragma unroll
                    for (int v = 0; v < VEC; v++)
                        wv[j][v] = Wsh[(kk + j) * HC + lane * VEC + v];
#pragma unroll
                for (int n = 0; n < 8; n++) {
                    float4 xv = *reinterpret_cast<const float4*>(&xsh[(wp * 8 + n) * KT + kk]);
#pragma unroll
                    for (int v = 0; v < VEC; v++)
                        acc[n][v] += xv.x * wv[0][v] + xv.y * wv[1][v]
                                   + xv.z * wv[2][v] + xv.w * wv[3][v];
                }
            }
            __syncthreads();
        }

#pragma unroll
        for (int n = 0; n < 8; n++) {
            int node = base + wp * 8 + n;
            if (node >= NN) break;
            if (VEC == 4) {
                *reinterpret_cast<float4*>(&g_h[(size_t)node * HC + lane * 4]) =
                    make_float4(acc[n][0], acc[n][1], acc[n][2], acc[n][3]);
            } else {
                *reinterpret_cast<float2*>(&g_h[(size_t)node * HC + lane * 2]) =
                    make_float2(acc[n][0], acc[n][1]);
            }
            alpha_epilogue<H, VEC>(node, lane, head, acc[n], asv, adv);
        }
    }
}

// =================== fused softmax-aggregate (warp per dst node) ===================
template <int HC, int H, bool ACT>
__global__ void k_agg(const float* __restrict__ bias) {
    constexpr int VEC = HC / 32;
    int lane = threadIdx.x & 31, wp = threadIdx.x >> 5;
    int node = blockIdx.x * 8 + wp;
    if (node >= NN) return;
    int head = (H == 2) ? (lane >> 4) : 0;

    float adv[H], esv[H], mv[H];
#pragma unroll
    for (int h = 0; h < H; h++) {
        adv[h] = g_ad[node * H + h];
        esv[h] = g_es[node * H + h];
        mv[h] = esv[h];
    }
    int beg = g_off[node], end = g_off[node + 1];

    // pass 1: per-head max over incoming edges (lane-strided, both heads)
    for (int i = beg + lane; i < end; i += 32) {
        int s = g_csr[i];
#pragma unroll
        for (int h = 0; h < H; h++)
            mv[h] = fmaxf(mv[h], lrelu(g_as[s * H + h] + adv[h]));
    }
#pragma unroll
    for (int h = 0; h < H; h++)
#pragma unroll
        for (int o = 16; o > 0; o >>= 1)
            mv[h] = fmaxf(mv[h], __shfl_xor_sync(0xffffffffu, mv[h], o));

    // pass 2: weighted gather
    const bool leader = (H == 2) ? ((lane & 15) == 0) : (lane == 0);
    const int  wsrc   = (H == 2) ? (head << 4) : 0;
    float acc[VEC];
#pragma unroll
    for (int v = 0; v < VEC; v++) acc[v] = 0.f;
    float denom = 0.f;
    float mh = mv[head];
    float adh = adv[head];

    int s = (beg < end) ? g_csr[beg] : 0;
#pragma unroll 2
    for (int i = beg; i < end; i++) {
        int snext = (i + 1 < end) ? g_csr[i + 1] : 0;
        float w = 0.f;
        if (leader) {
            float e = lrelu(g_as[s * H + head] + adh);
            w = expf(e - mh);
            denom += w;
        }
        w = __shfl_sync(0xffffffffu, w, wsrc);
        if (VEC == 4) {
            float4 hv = *reinterpret_cast<const float4*>(&g_h[(size_t)s * HC + lane * 4]);
            acc[0] += w * hv.x; acc[1] += w * hv.y; acc[2] += w * hv.z; acc[3] += w * hv.w;
        } else {
            float2 hv = *reinterpret_cast<const float2*>(&g_h[(size_t)s * HC + lane * 2]);
            acc[0] += w * hv.x; acc[1] += w * hv.y;
        }
        s = snext;
    }

    // self loop
    float ws = expf(esv[head] - mh);
    if (VEC == 4) {
        float4 hv = *reinterpret_cast<const float4*>(&g_h[(size_t)node * HC + lane * 4]);
        acc[0] += ws * hv.x; acc[1] += ws * hv.y; acc[2] += ws * hv.z; acc[3] += ws * hv.w;
    } else {
        float2 hv = *reinterpret_cast<const float2*>(&g_h[(size_t)node * HC + lane * 2]);
        acc[0] += ws * hv.x; acc[1] += ws * hv.y;
    }
    if (leader) denom += ws;
    float dh = __shfl_sync(0xffffffffu, denom, wsrc);
    float inv = 1.0f / (dh + 1e-16f);

    float outv[VEC];
#pragma unroll
    for (int v = 0; v < VEC; v++) {
        float t = acc[v] * inv + bias[lane * VEC + v];
        if (ACT) t = t > 0.f ? t : expm1f(t);
        outv[v] = t;
    }
    if (VEC == 4)
        *reinterpret_cast<float4*>(&g_x[(size_t)node * HC + lane * 4]) =
            make_float4(outv[0], outv[1], outv[2], outv[3]);
    else
        *reinterpret_cast<float2*>(&g_x[(size_t)node * HC + lane * 2]) =
            make_float2(outv[0], outv[1]);
}

// =================== pooling ===================
__global__ void k_pool_zero() {
    int idx = blockIdx.x * blockDim.x + threadIdx.x;
    if (idx < BB * 64) g_pool[idx] = 0.f;
    if (idx < BB) g_cnt[idx] = 0.f;
}
__global__ void k_pool(const int* __restrict__ batch) {
    int total = NN * 16;
    for (int idx = blockIdx.x * blockDim.x + threadIdx.x; idx < total; idx += gridDim.x * blockDim.x) {
        int n = idx / 16, q = idx - n * 16;
        int b = batch[n];
        float4 v = *reinterpret_cast<const float4*>(g_x + (size_t)n * 64 + q * 4);
        red4(g_pool + b * 64 + q * 4, v.x, v.y, v.z, v.w);
        if (q == 0) atomicAdd(&g_cnt[b], 1.0f);
    }
}

// =================== MLP head ===================
__global__ void k_mlp(const float* __restrict__ obs,
                      const float* __restrict__ Ws1, const float* __restrict__ bs1,
                      const float* __restrict__ lng, const float* __restrict__ lnb,
                      const float* __restrict__ Ws2, const float* __restrict__ bs2,
                      const float* __restrict__ Wa,  const float* __restrict__ ba,
                      const float* __restrict__ Wc,  const float* __restrict__ bc,
                      float* __restrict__ out) {
    __shared__ float comb[64 + OBSD];
    __shared__ float hb[MHD];
    __shared__ float h2[MHD];
    __shared__ float rb[8];
    __shared__ float stats[2];

    int b = blockIdx.x;
    int tid = threadIdx.x;

    if (tid < 64)             comb[tid] = g_pool[b * 64 + tid] / fmaxf(g_cnt[b], 1.0f);
    else if (tid < 64 + OBSD) comb[tid] = obs[b * OBSD + (tid - 64)];
    __syncthreads();

    float s = bs1[tid];
    for (int k = 0; k < 64 + OBSD; k++) s += comb[k] * Ws1[k * MHD + tid];

    float v = s;
#pragma unroll
    for (int o = 16; o > 0; o >>= 1) v += __shfl_down_sync(0xffffffffu, v, o);
    if ((tid & 31) == 0) rb[tid >> 5] = v;
    __syncthreads();
    if (tid == 0) { float t = 0.f; for (int w = 0; w < 8; w++) t += rb[w]; stats[0] = t / MHD; }
    __syncthreads();
    float mu = stats[0];
    float dv = s - mu;
    v = dv * dv;
#pragma unroll
    for (int o = 16; o > 0; o >>= 1) v += __shfl_down_sync(0xffffffffu, v, o);
    if ((tid & 31) == 0) rb[tid >> 5] = v;
    __syncthreads();
    if (tid == 0) { float t = 0.f; for (int w = 0; w < 8; w++) t += rb[w]; stats[1] = t / MHD; }
    __syncthreads();

    float hn = dv * rsqrtf(stats[1] + 1e-5f) * lng[tid] + lnb[tid];
    hb[tid] = fmaxf(hn, 0.f);
    __syncthreads();

    float s2 = bs2[tid];
    for (int k = 0; k < MHD; k++) s2 += hb[k] * Ws2[k * MHD + tid];
    h2[tid] = fmaxf(s2, 0.f);
    __syncthreads();

    if (tid < NAD) {
        float t = ba[tid];
        for (int k = 0; k < MHD; k++) t += h2[k] * Wa[k * NAD + tid];
        out[b * NAD + tid] = t;
    }
    if (tid == NAD) {
        float t = bc[0];
        for (int k = 0; k < MHD; k++) t += h2[k] * Wc[k];
        out[BB * NAD + b] = t;
    }
}

// =================== launch ===================
static inline int gs(long long n) { return (int)((n + 255) / 256); }

extern "C" void kernel_launch(void* const* d_in, const int* in_sizes, int n_in,
                              void* d_out, int out_size) {
    const float* obs   = (const float*)d_in[0];
    const float* nf    = (const float*)d_in[1];
    const int*   ei    = (const int*)  d_in[2];
    const int*   batch = (const int*)  d_in[3];
    const float* W0 = (const float*)d_in[4];
    const float* as0 = (const float*)d_in[5];
    const float* ad0 = (const float*)d_in[6];
    const float* b0  = (const float*)d_in[7];
    const float* W1 = (const float*)d_in[8];
    const float* as1 = (const float*)d_in[9];
    const float* ad1 = (const float*)d_in[10];
    const float* b1  = (const float*)d_in[11];
    const float* W2 = (const float*)d_in[12];
    const float* as2 = (const float*)d_in[13];
    const float* ad2 = (const float*)d_in[14];
    const float* b2  = (const float*)d_in[15];
    const float* Ws1 = (const float*)d_in[16];
    const float* bs1 = (const float*)d_in[17];
    const float* lng = (const float*)d_in[18];
    const float* lnb = (const float*)d_in[19];
    const float* Ws2 = (const float*)d_in[20];
    const float* bs2 = (const float*)d_in[21];
    const float* Wa  = (const float*)d_in[22];
    const float* ba  = (const float*)d_in[23];
    const float* Wc  = (const float*)d_in[24];
    const float* bc  = (const float*)d_in[25];
    float* out = (float*)d_out;

    // ---- CSR build (shared by all 3 layers) ----
    k_zero_deg<<<gs(NN + 1), 256>>>();
    k_hist<<<gs(EE), 256>>>(ei);
    k_scan1<<<98, 512>>>();
    k_scan2<<<1, 128>>>();
    k_scan3<<<98, 512>>>();
    k_fill<<<gs(EE), 256>>>(ei);

    const int AGGB = (NN + 7) / 8;  // 6250

    // ---- layer 0: FIN=8 -> H=2,C=64, ELU ----
    k_gemm0<<<782, 256>>>(nf, W0, as0, ad0);
    k_agg<128, 2, true><<<AGGB, 256>>>(b0);

    // ---- layer 1: 128 -> H=2,C=64, ELU ----
    k_gemm128<128, 2><<<782, 256>>>(W1, as1, ad1);
    k_agg<128, 2, true><<<AGGB, 256>>>(b1);

    // ---- layer 2: 128 -> H=1,C=64 ----
    k_gemm128<64, 1><<<782, 256>>>(W2, as2, ad2);
    k_agg<64, 1, false><<<AGGB, 256>>>(b2);

    // ---- pool + MLP ----
    k_pool_zero<<<gs(BB * 64), 256>>>();
    k_pool<<<gs((long long)NN * 16), 256>>>(batch);
    k_mlp<<<BB, MHD>>>(obs, Ws1, bs1, lng, lnb, Ws2, bs2, Wa, ba, Wc, bc, out);
}